// round 8
// baseline (speedup 1.0000x reference)
#include <cuda_runtime.h>
#include <cuda_bf16.h>

// ---------------------------------------------------------------------------
// LorentzLayer: out[b,a] = sum_{c,d} G[c][d][a] * T[b,c,d]
// G_c = Bi_mat @ (W_c * B_c) computed in closed form by a tiny kernel.
// Main kernel: HBM-bound streaming GEMV (262144 x 400) @ (400 x 4).
// Round 8: contiguous-lane layout. Each warp processes 2 rows; lane l owns
// cluster chunk*32+l, so every LDG.128 is a 512B contiguous warp transaction
// (4-5 lines vs 11 before) — removes the L1tex wavefront-replay bottleneck
// that pinned DRAM at ~70%. Component-folding butterfly reduction (9 shfl/row).
// Persistent grid=444, static interleaved units.
// ---------------------------------------------------------------------------

#define NCLUSTER 100
#define BATCH_N  262144
#define GPAD     20            // words per cluster in smem: conflict-free for
                               // 8-lane LDS.128 phases (stride 20 mod 32)

#define NBLOCKS  444           // 148 SMs * 3 resident blocks
#define NWARPS   (NBLOCKS * 8) // 3552 persistent warps
#define NUNITS   (BATCH_N / 2) // 131072 two-row units

__device__ float g_combined[NCLUSTER * 16];   // layout [c][d][a], a contiguous

__device__ __forceinline__ void build_boost(float B[4][4],
                                            float b0, float b1, float b2) {
    float mag2 = b0 * b0 + b1 * b1 + b2 * b2;
    float g = 1.0f / sqrtf(1.0f - mag2);
    float inv_mag2 = 1.0f / mag2;
    float gm1 = g - 1.0f;

    B[0][0] = g;
    B[0][1] = -g * b0; B[0][2] = -g * b1; B[0][3] = -g * b2;
    B[1][0] = -g * b0; B[2][0] = -g * b1; B[3][0] = -g * b2;

    float bb[3] = {b0, b1, b2};
    #pragma unroll
    for (int i = 0; i < 3; i++) {
        #pragma unroll
        for (int j = 0; j < 3; j++) {
            float v = gm1 * bb[i] * bb[j] * inv_mag2;
            if (i == j) v += 1.0f;
            B[i + 1][j + 1] = v;
        }
    }
}

__global__ void precompute_kernel(const float* __restrict__ Bo,
                                  const float* __restrict__ Bi,
                                  const float* __restrict__ W) {
    int c = threadIdx.x;
    if (c >= NCLUSTER) return;

    float Bim[4][4];
    build_boost(Bim, Bi[0], Bi[1], Bi[2]);

    float Bc[4][4];
    build_boost(Bc, Bo[c * 3 + 0], Bo[c * 3 + 1], Bo[c * 3 + 2]);

    float w = W[c];

    #pragma unroll
    for (int a = 0; a < 4; a++) {
        #pragma unroll
        for (int d = 0; d < 4; d++) {
            float s = 0.0f;
            #pragma unroll
            for (int m = 0; m < 4; m++)
                s += Bim[a][m] * Bc[m][d];
            g_combined[c * 16 + d * 4 + a] = s * w;   // [c][d][a]
        }
    }
}

// Per-chunk FMA body shared by main chunks and tail.
#define ACCUM_BODY(v0, v1, gp)                                          \
    do {                                                                \
        float4 g0 = (gp)[0];                                            \
        float4 g1 = (gp)[1];                                            \
        float4 g2 = (gp)[2];                                            \
        float4 g3 = (gp)[3];                                            \
        ax0 += v0.x * g0.x + v0.y * g1.x + v0.z * g2.x + v0.w * g3.x;   \
        ay0 += v0.x * g0.y + v0.y * g1.y + v0.z * g2.y + v0.w * g3.y;   \
        az0 += v0.x * g0.z + v0.y * g1.z + v0.z * g2.z + v0.w * g3.z;   \
        aw0 += v0.x * g0.w + v0.y * g1.w + v0.z * g2.w + v0.w * g3.w;   \
        ax1 += v1.x * g0.x + v1.y * g1.x + v1.z * g2.x + v1.w * g3.x;   \
        ay1 += v1.x * g0.y + v1.y * g1.y + v1.z * g2.y + v1.w * g3.y;   \
        az1 += v1.x * g0.z + v1.y * g1.z + v1.z * g2.z + v1.w * g3.z;   \
        aw1 += v1.x * g0.w + v1.y * g1.w + v1.z * g2.w + v1.w * g3.w;   \
    } while (0)

// Component-folding butterfly: returns in every lane the full-warp sum of
// component (lane&3). 9 shuffles per 4-vector.
__device__ __forceinline__ float reduce_vec4(float ax, float ay, float az,
                                             float aw, int lane) {
    const unsigned F = 0xffffffffu;
    float sx = ax + __shfl_xor_sync(F, ax, 1);
    float sy = ay + __shfl_xor_sync(F, ay, 1);
    float sz = az + __shfl_xor_sync(F, az, 1);
    float sw = aw + __shfl_xor_sync(F, aw, 1);
    float p = (lane & 1) ? sy : sx;
    float q = (lane & 1) ? sw : sz;
    p += __shfl_xor_sync(F, p, 2);
    q += __shfl_xor_sync(F, q, 2);
    float r = (lane & 2) ? q : p;
    r += __shfl_xor_sync(F, r, 4);
    r += __shfl_xor_sync(F, r, 8);
    r += __shfl_xor_sync(F, r, 16);
    return r;   // lane l holds component (l&3)
}

__global__ __launch_bounds__(256, 3)
void lorentz_main_kernel(const float* __restrict__ T, float* __restrict__ out) {
    __shared__ float gs[NCLUSTER * GPAD];

    int tid = threadIdx.x;
    for (int i = tid; i < NCLUSTER * 16; i += 256) {
        int c = i >> 4;
        int r = i & 15;
        gs[c * GPAD + r] = g_combined[i];
    }
    __syncthreads();

    int warp = tid >> 5;
    int lane = tid & 31;
    int wid = blockIdx.x * 8 + warp;

    for (int cur = wid; cur < NUNITS; cur += NWARPS) {
        int row0 = cur * 2;
        const float4* t0 = (const float4*)(T + (size_t)row0 * 400);
        const float4* t1 = t0 + 100;

        float ax0 = 0.f, ay0 = 0.f, az0 = 0.f, aw0 = 0.f;
        float ax1 = 0.f, ay1 = 0.f, az1 = 0.f, aw1 = 0.f;

        #pragma unroll
        for (int chunk = 0; chunk < 3; chunk++) {
            int c = chunk * 32 + lane;
            float4 v0 = __ldcs(&t0[c]);
            float4 v1 = __ldcs(&t1[c]);
            const float4* gp = (const float4*)(&gs[c * GPAD]);
            ACCUM_BODY(v0, v1, gp);
        }

        // tail: clusters 96..99 on lanes 0..3
        if (lane < 4) {
            int c = 96 + lane;
            float4 v0 = __ldcs(&t0[c]);
            float4 v1 = __ldcs(&t1[c]);
            const float4* gp = (const float4*)(&gs[c * GPAD]);
            ACCUM_BODY(v0, v1, gp);
        }

        float r0 = reduce_vec4(ax0, ay0, az0, aw0, lane);
        float r1 = reduce_vec4(ax1, ay1, az1, aw1, lane);

        if (lane < 4) {
            out[(size_t)row0 * 4 + lane] = r0;
            out[(size_t)row0 * 4 + 4 + lane] = r1;
        }
    }
}

extern "C" void kernel_launch(void* const* d_in, const int* in_sizes, int n_in,
                              void* d_out, int out_size) {
    const float* T  = (const float*)d_in[0];   // (262144, 100, 4)
    const float* Bo = (const float*)d_in[1];   // (100, 3)
    const float* Bi = (const float*)d_in[2];   // (1, 3)
    const float* W  = (const float*)d_in[3];   // (100, 1)
    // d_in[4] = K_mats — encoded analytically in build_boost.

    float* out = (float*)d_out;                // (262144, 1, 4)

    precompute_kernel<<<1, 128>>>(Bo, Bi, W);

    lorentz_main_kernel<<<NBLOCKS, 256>>>(T, out);
}

// round 9
// speedup vs baseline: 1.0013x; 1.0013x over previous
#include <cuda_runtime.h>
#include <cuda_bf16.h>

// ---------------------------------------------------------------------------
// LorentzLayer: out[b,a] = sum_{c,d} G[c][d][a] * T[b,c,d]
// G_c = Bi_mat @ (W_c * B_c), built in closed form.
// Round 9: single persistent kernel. G is REGISTER-RESIDENT per lane
// (clusters lane, 32+lane, 64+lane; tail 96..99 via 64B smem broadcast),
// eliminating all main-loop LDS traffic — R8 analysis showed LDS wavefronts
// (~60% of L1tex cycles) were the request-rate limiter pinning DRAM at ~70%.
// occ 2 blocks/SM (<=128 regs), grid = 296 (one resident wave), static
// interleaved 2-row units, contiguous 512B warp loads, butterfly reduction.
// ---------------------------------------------------------------------------

#define NCLUSTER 100
#define BATCH_N  262144
#define NBLOCKS  296            // 148 SMs * 2 resident blocks
#define NWARPS   (NBLOCKS * 8)  // 2368 persistent warps
#define NUNITS   (BATCH_N / 2)  // 131072 two-row units

__device__ __forceinline__ void build_boost(float B[4][4],
                                            float b0, float b1, float b2) {
    float mag2 = b0 * b0 + b1 * b1 + b2 * b2;
    float g = 1.0f / sqrtf(1.0f - mag2);
    float inv_mag2 = 1.0f / mag2;
    float gm1 = g - 1.0f;

    B[0][0] = g;
    B[0][1] = -g * b0; B[0][2] = -g * b1; B[0][3] = -g * b2;
    B[1][0] = -g * b0; B[2][0] = -g * b1; B[3][0] = -g * b2;

    float bb[3] = {b0, b1, b2};
    #pragma unroll
    for (int i = 0; i < 3; i++) {
        #pragma unroll
        for (int j = 0; j < 3; j++) {
            float v = gm1 * bb[i] * bb[j] * inv_mag2;
            if (i == j) v += 1.0f;
            B[i + 1][j + 1] = v;
        }
    }
}

// Gd[d].{x,y,z,w} = (Bim @ (w * Bc))[a=0..3][d]   (column d, components = a)
__device__ __forceinline__ void make_G(const float Bim[4][4],
                                       const float* __restrict__ Bo,
                                       float w, int c, float4 Gd[4]) {
    float Bc[4][4];
    build_boost(Bc, Bo[3 * c + 0], Bo[3 * c + 1], Bo[3 * c + 2]);
    #pragma unroll
    for (int d = 0; d < 4; d++) {
        float s0 = 0.f, s1 = 0.f, s2 = 0.f, s3 = 0.f;
        #pragma unroll
        for (int m = 0; m < 4; m++) {
            s0 += Bim[0][m] * Bc[m][d];
            s1 += Bim[1][m] * Bc[m][d];
            s2 += Bim[2][m] * Bc[m][d];
            s3 += Bim[3][m] * Bc[m][d];
        }
        Gd[d] = make_float4(s0 * w, s1 * w, s2 * w, s3 * w);
    }
}

#define ACCUM4(v0, v1, G)                                               \
    do {                                                                \
        ax0 += v0.x * G[0].x + v0.y * G[1].x + v0.z * G[2].x + v0.w * G[3].x; \
        ay0 += v0.x * G[0].y + v0.y * G[1].y + v0.z * G[2].y + v0.w * G[3].y; \
        az0 += v0.x * G[0].z + v0.y * G[1].z + v0.z * G[2].z + v0.w * G[3].z; \
        aw0 += v0.x * G[0].w + v0.y * G[1].w + v0.z * G[2].w + v0.w * G[3].w; \
        ax1 += v1.x * G[0].x + v1.y * G[1].x + v1.z * G[2].x + v1.w * G[3].x; \
        ay1 += v1.x * G[0].y + v1.y * G[1].y + v1.z * G[2].y + v1.w * G[3].y; \
        az1 += v1.x * G[0].z + v1.y * G[1].z + v1.z * G[2].z + v1.w * G[3].z; \
        aw1 += v1.x * G[0].w + v1.y * G[1].w + v1.z * G[2].w + v1.w * G[3].w; \
    } while (0)

// Component-folding butterfly: every lane ends with the full-warp sum of
// component (lane&3). 9 shuffles per 4-vector. (Verified in R8.)
__device__ __forceinline__ float reduce_vec4(float ax, float ay, float az,
                                             float aw, int lane) {
    const unsigned F = 0xffffffffu;
    float sx = ax + __shfl_xor_sync(F, ax, 1);
    float sy = ay + __shfl_xor_sync(F, ay, 1);
    float sz = az + __shfl_xor_sync(F, az, 1);
    float sw = aw + __shfl_xor_sync(F, aw, 1);
    float p = (lane & 1) ? sy : sx;
    float q = (lane & 1) ? sw : sz;
    p += __shfl_xor_sync(F, p, 2);
    q += __shfl_xor_sync(F, q, 2);
    float r = (lane & 2) ? q : p;
    r += __shfl_xor_sync(F, r, 4);
    r += __shfl_xor_sync(F, r, 8);
    r += __shfl_xor_sync(F, r, 16);
    return r;   // lane l holds component (l&3)
}

__global__ __launch_bounds__(256, 2)
void lorentz_main_kernel(const float* __restrict__ T,
                         const float* __restrict__ Bo,
                         const float* __restrict__ Bi,
                         const float* __restrict__ W,
                         float* __restrict__ out) {
    __shared__ float4 gtail[4][4];   // G for clusters 96..99, [c-96][d]

    int tid  = threadIdx.x;
    int lane = tid & 31;
    int warp = tid >> 5;

    // --- prologue: build register-resident G (once per persistent block) ---
    float Bim[4][4];
    build_boost(Bim, Bi[0], Bi[1], Bi[2]);

    float4 G0[4], G1[4], G2[4], GT[4];
    make_G(Bim, Bo, W[lane],      lane,      G0);
    make_G(Bim, Bo, W[32 + lane], 32 + lane, G1);
    make_G(Bim, Bo, W[64 + lane], 64 + lane, G2);

    if (tid < 4) {
        float4 gt[4];
        make_G(Bim, Bo, W[96 + tid], 96 + tid, gt);
        gtail[tid][0] = gt[0];
        gtail[tid][1] = gt[1];
        gtail[tid][2] = gt[2];
        gtail[tid][3] = gt[3];
    }
    __syncthreads();
    // broadcast (finite for every lane; lanes >=4 use it with v=0)
    GT[0] = gtail[lane & 3][0];
    GT[1] = gtail[lane & 3][1];
    GT[2] = gtail[lane & 3][2];
    GT[3] = gtail[lane & 3][3];

    const float4 ZERO = make_float4(0.f, 0.f, 0.f, 0.f);
    int wid = blockIdx.x * 8 + warp;

    // --- main loop: LDG-only, zero LDS ---
    for (int cur = wid; cur < NUNITS; cur += NWARPS) {
        const float4* t0 = (const float4*)T + (size_t)cur * 200;
        const float4* t1 = t0 + 100;

        float4 v00 = __ldcs(t0 + lane);
        float4 v01 = __ldcs(t0 + 32 + lane);
        float4 v02 = __ldcs(t0 + 64 + lane);
        float4 v10 = __ldcs(t1 + lane);
        float4 v11 = __ldcs(t1 + 32 + lane);
        float4 v12 = __ldcs(t1 + 64 + lane);
        float4 vt0 = ZERO, vt1 = ZERO;
        if (lane < 4) {
            vt0 = __ldcs(t0 + 96 + lane);
            vt1 = __ldcs(t1 + 96 + lane);
        }

        float ax0 = 0.f, ay0 = 0.f, az0 = 0.f, aw0 = 0.f;
        float ax1 = 0.f, ay1 = 0.f, az1 = 0.f, aw1 = 0.f;

        ACCUM4(v00, v10, G0);
        ACCUM4(v01, v11, G1);
        ACCUM4(v02, v12, G2);
        ACCUM4(vt0, vt1, GT);

        float r0 = reduce_vec4(ax0, ay0, az0, aw0, lane);
        float r1 = reduce_vec4(ax1, ay1, az1, aw1, lane);

        if (lane < 4) {
            out[(size_t)cur * 8 + lane]     = r0;
            out[(size_t)cur * 8 + 4 + lane] = r1;
        }
    }
}

extern "C" void kernel_launch(void* const* d_in, const int* in_sizes, int n_in,
                              void* d_out, int out_size) {
    const float* T  = (const float*)d_in[0];   // (262144, 100, 4)
    const float* Bo = (const float*)d_in[1];   // (100, 3)
    const float* Bi = (const float*)d_in[2];   // (1, 3)
    const float* W  = (const float*)d_in[3];   // (100, 1)
    // d_in[4] = K_mats — encoded analytically in build_boost.

    float* out = (float*)d_out;                // (262144, 1, 4)

    lorentz_main_kernel<<<NBLOCKS, 256>>>(T, Bo, Bi, W, out);
}